// round 11
// baseline (speedup 1.0000x reference)
#include <cuda_runtime.h>
#include <cuda_fp16.h>
#include <cstdint>

// ---------------------------------------------------------------------------
// AdaConv2d (sm_103, legacy mma.sync path):
//   K1 stats -> prepack (fp16 weights) -> K2 instancenorm + adaptive grouped
//   conv (fp16 y, NHWC reflect-pre-padded) -> halo -> K3 fp16 implicit-GEMM.
// R10: K3 triple-buffered A/B with deep prefetch (A +2 iters, B +2 groups),
//      one commit per iteration, cp.async.wait_group 1 (no self-wait);
//      ada split into 2 oc-passes to kill register spills.
// ---------------------------------------------------------------------------

constexpr int B   = 8;
constexpr int C   = 256;
constexpr int H   = 128;
constexpr int W   = 128;
constexpr int G   = 32;
constexpr int CPG = 8;
constexpr int OUT = 256;
constexpr int HW  = H * W;
constexpr float EPS = 1e-5f;

constexpr int HP = H + 2;
constexpr int WP = W + 2;

constexpr int MTILE = 128;   // oc per CTA (K3)
constexpr int CCH   = 64;    // ci per smem stage (K3)

typedef unsigned long long ull;

// Device scratch
static __device__ float g_mean[B * C];
static __device__ float g_rsig[B * C];
static __device__ __half g_yh[(size_t)B * HP * WP * C];   // NHWC padded, fp16
static __device__ __half g_wh[9 * OUT * C];               // [tap][oc][ci] fp16

__device__ __forceinline__ int reflect_idx(int v, int n) {
    v = v < 0 ? -v : v;
    v = v >= n ? 2 * n - 2 - v : v;
    return v;
}

#define SWZ128(off) ((off) ^ (((off) >> 3) & 0x70))

__device__ __forceinline__ uint32_t smem_u32(const void* p) {
    uint32_t a;
    asm("{ .reg .u64 t; cvta.to.shared.u64 t, %1; cvt.u32.u64 %0, t; }"
        : "=r"(a) : "l"(p));
    return a;
}
__device__ __forceinline__ void cpa16(uint32_t dst, const void* src) {
    asm volatile("cp.async.cg.shared.global [%0], [%1], 16;"
                 :: "r"(dst), "l"(src));
}
#define CP_COMMIT() asm volatile("cp.async.commit_group;" ::: "memory")
#define CP_WAIT1()  asm volatile("cp.async.wait_group 1;" ::: "memory")

__device__ __forceinline__ void ldmx4(uint32_t* r, uint32_t addr) {
    asm volatile("ldmatrix.sync.aligned.m8n8.x4.shared.b16 {%0,%1,%2,%3}, [%4];"
                 : "=r"(r[0]), "=r"(r[1]), "=r"(r[2]), "=r"(r[3]) : "r"(addr));
}
__device__ __forceinline__ void mma16816(float* d, const uint32_t* a,
                                         const uint32_t* b) {
    asm volatile(
        "mma.sync.aligned.m16n8k16.row.col.f32.f16.f16.f32 "
        "{%0,%1,%2,%3},{%4,%5,%6,%7},{%8,%9},{%0,%1,%2,%3};"
        : "+f"(d[0]), "+f"(d[1]), "+f"(d[2]), "+f"(d[3])
        : "r"(a[0]), "r"(a[1]), "r"(a[2]), "r"(a[3]), "r"(b[0]), "r"(b[1]));
}

// packed f32x2 helpers (Blackwell base ISA, sm_100+)
__device__ __forceinline__ ull pack2(float lo, float hi) {
    ull d;
    asm("mov.b64 %0, {%1, %2};" : "=l"(d) : "f"(lo), "f"(hi));
    return d;
}
__device__ __forceinline__ ull fma2(ull a, ull b, ull c) {
    ull d;
    asm("fma.rn.f32x2 %0, %1, %2, %3;" : "=l"(d) : "l"(a), "l"(b), "l"(c));
    return d;
}
__device__ __forceinline__ float2 unpack2(ull v) {
    float2 r;
    asm("mov.b64 {%0, %1}, %2;" : "=f"(r.x), "=f"(r.y) : "l"(v));
    return r;
}

// ---------------------------------------------------------------------------
// K1: per-(b,c) mean / rsqrt(var+eps)
// ---------------------------------------------------------------------------
__global__ void stats_kernel(const float* __restrict__ x) {
    int bc = blockIdx.x;
    const float4* xp = reinterpret_cast<const float4*>(x + (size_t)bc * HW);
    float s = 0.f, ss = 0.f;
    #pragma unroll 4
    for (int i = threadIdx.x; i < HW / 4; i += 256) {
        float4 v = xp[i];
        s  += (v.x + v.y) + (v.z + v.w);
        ss += v.x * v.x + v.y * v.y + v.z * v.z + v.w * v.w;
    }
    #pragma unroll
    for (int o = 16; o; o >>= 1) {
        s  += __shfl_down_sync(0xFFFFFFFFu, s, o);
        ss += __shfl_down_sync(0xFFFFFFFFu, ss, o);
    }
    __shared__ float sh_s[8], sh_ss[8];
    int wid = threadIdx.x >> 5, lid = threadIdx.x & 31;
    if (lid == 0) { sh_s[wid] = s; sh_ss[wid] = ss; }
    __syncthreads();
    if (threadIdx.x == 0) {
        float ts = 0.f, tss = 0.f;
        #pragma unroll
        for (int i = 0; i < 8; i++) { ts += sh_s[i]; tss += sh_ss[i]; }
        float m   = ts * (1.f / HW);
        float var = tss * (1.f / HW) - m * m;
        g_mean[bc] = m;
        g_rsig[bc] = rsqrtf(var + EPS);
    }
}

// ---------------------------------------------------------------------------
// Weight prepack: conv_w [OUT][C][3][3] fp32 -> [tap][oc][ci] fp16
// ---------------------------------------------------------------------------
__global__ void prepack_kernel(const float* __restrict__ cw) {
    int idx = blockIdx.x * 256 + threadIdx.x;
    int tap = idx >> 16;
    int r   = idx & 0xFFFF;
    int oc  = r >> 8, ci = r & 255;
    g_wh[idx] = __float2half_rn(cw[(oc * C + ci) * 9 + tap]);
}

// ---------------------------------------------------------------------------
// K2: normalize + adaptive grouped 3x3 + 1x1 + bias -> fp16 NHWC padded.
// 32x32 tile, 128 threads, 8 px/thread, packed f32x2 fma, 2 oc-passes of 4.
// ---------------------------------------------------------------------------
constexpr int T2W = 32, T2H = 32;

__global__ __launch_bounds__(128, 4)
void ada_kernel(const float* __restrict__ x,
                const float* __restrict__ ws,
                const float* __restrict__ wp,
                const float* __restrict__ bias) {
    __shared__ float s_in[CPG][T2H + 2][35];   // stride 35: conflict-free
    __shared__ ull   s_w2[CPG][CPG][9];        // [o][j][k], weight duplicated
    __shared__ float s_wp[CPG][CPG];

    int bg = blockIdx.z;
    int b = bg >> 5, g = bg & 31;
    int x0 = blockIdx.x * T2W, y0 = blockIdx.y * T2H;
    int tid = threadIdx.x;

    if (tid < CPG * CPG) {
        int o = tid >> 3, i = tid & 7;
        s_wp[o][i] = wp[(b * C + g * CPG + o) * CPG + i];
    }
    __syncthreads();

    // fold 1x1 into spatial weights, store duplicated (w,w) pairs
    for (int t = tid; t < CPG * CPG * 9; t += 128) {
        int o = t / 72, r = t % 72, j = r / 9, k = r % 9;
        float acc = 0.f;
        #pragma unroll
        for (int i = 0; i < CPG; i++)
            acc += s_wp[o][i] * ws[((b * C + g * CPG + i) * CPG + j) * 9 + k];
        s_w2[o][j][k] = pack2(acc, acc);
    }

    // normalized input tile with reflect halo: 8 ch x 34 x 34
    for (int e = tid; e < CPG * (T2H + 2) * 34; e += 128) {
        int j   = e / ((T2H + 2) * 34);
        int r   = (e / 34) % (T2H + 2);
        int col = e % 34;
        int gy = reflect_idx(y0 + r - 1, H);
        int gx = reflect_idx(x0 + col - 1, W);
        int cg = b * C + g * CPG + j;
        s_in[j][r][col] = (x[(size_t)cg * HW + gy * W + gx] - g_mean[cg]) * g_rsig[cg];
    }
    __syncthreads();

    int px = (tid & 3) * 8;     // 0,8,16,24
    int py = tid >> 2;          // 0..31
    size_t pbase = ((size_t)(b * HP + (y0 + py + 1)) * WP + (x0 + px + 1)) * C
                   + g * CPG;

    #pragma unroll
    for (int og = 0; og < 2; og++) {
        ull acc[4][4];
        #pragma unroll
        for (int o4 = 0; o4 < 4; o4++)
            #pragma unroll
            for (int q = 0; q < 4; q++)
                acc[o4][q] = 0ull;

        #pragma unroll
        for (int j = 0; j < CPG; j++) {
            #pragma unroll
            for (int ky = 0; ky < 3; ky++) {
                const float* row = &s_in[j][py + ky][px];
                float in[10];
                #pragma unroll
                for (int k = 0; k < 10; k++) in[k] = row[k];
                ull P0[4], P1[4];
                #pragma unroll
                for (int q = 0; q < 4; q++) {
                    P0[q] = pack2(in[2 * q],     in[2 * q + 1]);
                    P1[q] = pack2(in[2 * q + 1], in[2 * q + 2]);
                }
                ull P2_3 = pack2(in[8], in[9]);
                #pragma unroll
                for (int o4 = 0; o4 < 4; o4++) {
                    int o = og * 4 + o4;
                    ull w0 = s_w2[o][j][ky * 3 + 0];
                    ull w1 = s_w2[o][j][ky * 3 + 1];
                    ull w2 = s_w2[o][j][ky * 3 + 2];
                    #pragma unroll
                    for (int q = 0; q < 4; q++) {
                        acc[o4][q] = fma2(w0, P0[q], acc[o4][q]);
                        acc[o4][q] = fma2(w1, P1[q], acc[o4][q]);
                        acc[o4][q] = fma2(w2, (q < 3) ? P0[q + 1] : P2_3,
                                          acc[o4][q]);
                    }
                }
            }
        }

        float bz[4];
        #pragma unroll
        for (int o4 = 0; o4 < 4; o4++)
            bz[o4] = bias[b * C + g * CPG + og * 4 + o4];

        union U8 { __half h[4]; uint2 u; };
        #pragma unroll
        for (int q = 0; q < 4; q++) {
            U8 ua, ub;
            #pragma unroll
            for (int o4 = 0; o4 < 4; o4++) {
                float2 v = unpack2(acc[o4][q]);
                ua.h[o4] = __float2half_rn(v.x + bz[o4]);
                ub.h[o4] = __float2half_rn(v.y + bz[o4]);
            }
            *reinterpret_cast<uint2*>(g_yh + pbase + (2 * q)     * C + og * 4) = ua.u;
            *reinterpret_cast<uint2*>(g_yh + pbase + (2 * q + 1) * C + og * 4) = ub.u;
        }
    }
}

// ---------------------------------------------------------------------------
// Halo fill (reflect) for the padded NHWC plane
// ---------------------------------------------------------------------------
__global__ void halo_kernel() {
    int e = blockIdx.x;      // 0..515
    int b = blockIdx.y;
    int py, px;
    if (e < 130)       { py = 0;            px = e; }
    else if (e < 260)  { py = 129;          px = e - 130; }
    else if (e < 388)  { py = e - 260 + 1;  px = 0; }
    else               { py = e - 388 + 1;  px = 129; }
    int sy = reflect_idx(py - 1, H) + 1;
    int sx = reflect_idx(px - 1, W) + 1;
    size_t dst = ((size_t)(b * HP + py) * WP + px) * C + threadIdx.x;
    size_t src = ((size_t)(b * HP + sy) * WP + sx) * C + threadIdx.x;
    g_yh[dst] = g_yh[src];
}

// ---------------------------------------------------------------------------
// K3: fp16 implicit-GEMM final conv, deep cp.async pipeline.
// CTA: 128 oc x 128 px, 8 warps (2M x 4N), warp tile 64x32, CCH=64.
// Triple-buffered A (prefetch +2 iters) and B (prefetch +2 groups);
// exactly one commit_group per iteration; wait_group 1.
// ---------------------------------------------------------------------------
constexpr int A_BUF  = 16384;
constexpr int OFF_A  = 0;                        // 3 buffers -> 49152
constexpr int B_BUF  = 130 * 128;                // 16640
constexpr int OFF_B  = 49152;                    // 3 buffers -> +49920
constexpr int SMEM_K3 = OFF_B + 3 * B_BUF;       // 99072

__global__ __launch_bounds__(256, 2)
void final_mma_kernel(const float* __restrict__ cb, float* __restrict__ out) {
    extern __shared__ char sb[];
    uint32_t su = smem_u32(sb);
    int tid  = threadIdx.x;
    int warp = tid >> 5, lane = tid & 31;
    int wm = warp >> 2;
    int wn = warp & 3;

    int y0  = blockIdx.x;
    int b   = blockIdx.y;
    int ocb = blockIdx.z;

    int a_r[4], a_j[4];
    uint32_t a_soff[4];
    #pragma unroll
    for (int q = 0; q < 4; q++) {
        int e = tid + q * 256;
        a_r[q] = e >> 3; a_j[q] = e & 7;
        a_soff[q] = SWZ128((uint32_t)(a_r[q] * 128 + a_j[q] * 16));
    }

    auto issue_A = [&](int tap, int c0, uint32_t abase) {
        #pragma unroll
        for (int q = 0; q < 4; q++) {
            size_t gi = ((size_t)(tap * OUT + ocb * MTILE + a_r[q])) * C
                        + c0 + a_j[q] * 8;
            cpa16(abase + a_soff[q], g_wh + gi);
        }
    };
    auto issue_B = [&](int c0, int dyi, uint32_t bbase) {
        for (int e = tid; e < 130 * 8; e += 256) {
            int r = e >> 3, j = e & 7;
            size_t gi = ((size_t)(b * HP + y0 + dyi) * WP + r) * C + c0 + j * 8;
            uint32_t off = SWZ128((uint32_t)(r * 128 + j * 16));
            cpa16(bbase + off, g_yh + gi);
        }
    };

    float acc[4][4][4];
    #pragma unroll
    for (int mi = 0; mi < 4; mi++)
        #pragma unroll
        for (int ni = 0; ni < 4; ni++)
            #pragma unroll
            for (int q = 0; q < 4; q++)
                acc[mi][ni][q] = 0.f;

    uint32_t a_row = (uint32_t)(wm * 64 + (lane & 15));
    uint32_t a_kh  = (uint32_t)(lane >> 4) * 16;
    uint32_t b_row = (uint32_t)(wn * 32 + (lane & 7) + ((lane >> 4) << 3));
    uint32_t b_kh  = (uint32_t)((lane >> 3) & 1) * 16;

    // prologue: C0 = {A(0), B(grp0)}, C1 = {A(1), B(grp1)}
    issue_A(0, 0, su + OFF_A);
    issue_B(0, 0, su + OFF_B);
    CP_COMMIT();
    issue_A(1, 0, su + OFF_A + A_BUF);
    issue_B(0, 1, su + OFF_B + B_BUF);      // grp1: c0=0, dy=1
    CP_COMMIT();

    for (int it = 0; it < 36; it++) {
        int gi  = it / 3;                   // group = c0i*3 + dy (0..11)
        int dxi = it % 3;
        uint32_t abase = su + OFF_A + (it % 3) * A_BUF;
        uint32_t bbase = su + OFF_B + (gi % 3) * B_BUF;

        CP_WAIT1();
        __syncthreads();

        // exactly one commit per iteration: C_{it+2} = {A(it+2)} [+ B(gi+2)]
        int ia = it + 2;
        if (ia < 36)
            issue_A(ia % 9, (ia / 9) * CCH, su + OFF_A + (ia % 3) * A_BUF);
        if (dxi == 0 && gi + 2 < 12) {
            int ng = gi + 2;
            issue_B((ng / 3) * CCH, ng % 3, su + OFF_B + (ng % 3) * B_BUF);
        }
        CP_COMMIT();

        #pragma unroll
        for (int ks = 0; ks < 4; ks++) {
            uint32_t kb = (uint32_t)ks * 32;
            uint32_t aF[4][4], bF[2][4];
            #pragma unroll
            for (int mi = 0; mi < 4; mi++) {
                uint32_t off = SWZ128((a_row + mi * 16) * 128 + kb + a_kh);
                ldmx4(aF[mi], abase + off);
            }
            #pragma unroll
            for (int nh = 0; nh < 2; nh++) {
                uint32_t off = SWZ128((b_row + nh * 16 + dxi) * 128 + kb + b_kh);
                ldmx4(bF[nh], bbase + off);
            }
            #pragma unroll
            for (int mi = 0; mi < 4; mi++)
                #pragma unroll
                for (int ni = 0; ni < 4; ni++)
                    mma16816(acc[mi][ni], aF[mi], &bF[ni >> 1][(ni & 1) * 2]);
        }
    }

    int row0 = lane >> 2;
    int col2 = (lane & 3) * 2;
    #pragma unroll
    for (int mi = 0; mi < 4; mi++) {
        int oc = ocb * MTILE + wm * 64 + mi * 16 + row0;
        float bz0 = cb[oc];
        float bz1 = cb[oc + 8];
        size_t base0 = (((size_t)(b * OUT + oc))     * H + y0) * W;
        size_t base1 = (((size_t)(b * OUT + oc + 8)) * H + y0) * W;
        #pragma unroll
        for (int ni = 0; ni < 4; ni++) {
            int px = wn * 32 + ni * 8 + col2;
            float2 v0 = { acc[mi][ni][0] + bz0, acc[mi][ni][1] + bz0 };
            float2 v1 = { acc[mi][ni][2] + bz1, acc[mi][ni][3] + bz1 };
            *reinterpret_cast<float2*>(out + base0 + px) = v0;
            *reinterpret_cast<float2*>(out + base1 + px) = v1;
        }
    }
}

// ---------------------------------------------------------------------------
extern "C" void kernel_launch(void* const* d_in, const int* in_sizes, int n_in,
                              void* d_out, int out_size) {
    const float* x    = (const float*)d_in[0];
    const float* ws   = (const float*)d_in[1];
    const float* wp   = (const float*)d_in[2];
    const float* bias = (const float*)d_in[3];
    const float* cw   = (const float*)d_in[4];
    const float* cb   = (const float*)d_in[5];
    float* out = (float*)d_out;

    cudaFuncSetAttribute(final_mma_kernel,
                         cudaFuncAttributeMaxDynamicSharedMemorySize, SMEM_K3);

    stats_kernel<<<B * C, 256>>>(x);
    prepack_kernel<<<9 * OUT * C / 256, 256>>>(cw);
    ada_kernel<<<dim3(W / T2W, H / T2H, B * G), 128>>>(x, ws, wp, bias);
    halo_kernel<<<dim3(516, B), 256>>>();
    final_mma_kernel<<<dim3(H, B, OUT / MTILE), 256, SMEM_K3>>>(cb, out);
}

// round 13
// speedup vs baseline: 1.1342x; 1.1342x over previous
#include <cuda_runtime.h>
#include <cuda_fp16.h>
#include <cstdint>

// ---------------------------------------------------------------------------
// AdaConv2d (sm_103, legacy mma.sync path):
//   K1 stats -> prepack (fp16 weights) -> K2 instancenorm + adaptive grouped
//   conv (fp16 y, NHWC reflect-pre-padded) -> halo -> K3 fp16 implicit-GEMM.
// R12: exact R9 revert + k-step software pipeline in K3 (fragment double
//      buffer: prefetch ks+1 LDSMs before ks MMA block).
// ---------------------------------------------------------------------------

constexpr int B   = 8;
constexpr int C   = 256;
constexpr int H   = 128;
constexpr int W   = 128;
constexpr int G   = 32;
constexpr int CPG = 8;
constexpr int OUT = 256;
constexpr int HW  = H * W;
constexpr float EPS = 1e-5f;

constexpr int HP = H + 2;
constexpr int WP = W + 2;

constexpr int MTILE = 128;   // oc per CTA (K3)
constexpr int CCH   = 64;    // ci per smem stage (K3)

typedef unsigned long long ull;

// Device scratch
static __device__ float g_mean[B * C];
static __device__ float g_rsig[B * C];
static __device__ __half g_yh[(size_t)B * HP * WP * C];   // NHWC padded, fp16
static __device__ __half g_wh[9 * OUT * C];               // [tap][oc][ci] fp16

__device__ __forceinline__ int reflect_idx(int v, int n) {
    v = v < 0 ? -v : v;
    v = v >= n ? 2 * n - 2 - v : v;
    return v;
}

#define SWZ128(off) ((off) ^ (((off) >> 3) & 0x70))

__device__ __forceinline__ uint32_t smem_u32(const void* p) {
    uint32_t a;
    asm("{ .reg .u64 t; cvta.to.shared.u64 t, %1; cvt.u32.u64 %0, t; }"
        : "=r"(a) : "l"(p));
    return a;
}
__device__ __forceinline__ void cpa16(uint32_t dst, const void* src) {
    asm volatile("cp.async.cg.shared.global [%0], [%1], 16;"
                 :: "r"(dst), "l"(src));
}
#define CP_COMMIT() asm volatile("cp.async.commit_group;" ::: "memory")
#define CP_WAIT0()  asm volatile("cp.async.wait_group 0;" ::: "memory")

__device__ __forceinline__ void ldmx4(uint32_t* r, uint32_t addr) {
    asm volatile("ldmatrix.sync.aligned.m8n8.x4.shared.b16 {%0,%1,%2,%3}, [%4];"
                 : "=r"(r[0]), "=r"(r[1]), "=r"(r[2]), "=r"(r[3]) : "r"(addr));
}
__device__ __forceinline__ void mma16816(float* d, const uint32_t* a,
                                         const uint32_t* b) {
    asm volatile(
        "mma.sync.aligned.m16n8k16.row.col.f32.f16.f16.f32 "
        "{%0,%1,%2,%3},{%4,%5,%6,%7},{%8,%9},{%0,%1,%2,%3};"
        : "+f"(d[0]), "+f"(d[1]), "+f"(d[2]), "+f"(d[3])
        : "r"(a[0]), "r"(a[1]), "r"(a[2]), "r"(a[3]), "r"(b[0]), "r"(b[1]));
}

// packed f32x2 helpers (Blackwell base ISA, sm_100+)
__device__ __forceinline__ ull pack2(float lo, float hi) {
    ull d;
    asm("mov.b64 %0, {%1, %2};" : "=l"(d) : "f"(lo), "f"(hi));
    return d;
}
__device__ __forceinline__ ull fma2(ull a, ull b, ull c) {
    ull d;
    asm("fma.rn.f32x2 %0, %1, %2, %3;" : "=l"(d) : "l"(a), "l"(b), "l"(c));
    return d;
}
__device__ __forceinline__ float2 unpack2(ull v) {
    float2 r;
    asm("mov.b64 {%0, %1}, %2;" : "=f"(r.x), "=f"(r.y) : "l"(v));
    return r;
}

// ---------------------------------------------------------------------------
// K1: per-(b,c) mean / rsqrt(var+eps)
// ---------------------------------------------------------------------------
__global__ void stats_kernel(const float* __restrict__ x) {
    int bc = blockIdx.x;
    const float4* xp = reinterpret_cast<const float4*>(x + (size_t)bc * HW);
    float s = 0.f, ss = 0.f;
    #pragma unroll 4
    for (int i = threadIdx.x; i < HW / 4; i += 256) {
        float4 v = xp[i];
        s  += (v.x + v.y) + (v.z + v.w);
        ss += v.x * v.x + v.y * v.y + v.z * v.z + v.w * v.w;
    }
    #pragma unroll
    for (int o = 16; o; o >>= 1) {
        s  += __shfl_down_sync(0xFFFFFFFFu, s, o);
        ss += __shfl_down_sync(0xFFFFFFFFu, ss, o);
    }
    __shared__ float sh_s[8], sh_ss[8];
    int wid = threadIdx.x >> 5, lid = threadIdx.x & 31;
    if (lid == 0) { sh_s[wid] = s; sh_ss[wid] = ss; }
    __syncthreads();
    if (threadIdx.x == 0) {
        float ts = 0.f, tss = 0.f;
        #pragma unroll
        for (int i = 0; i < 8; i++) { ts += sh_s[i]; tss += sh_ss[i]; }
        float m   = ts * (1.f / HW);
        float var = tss * (1.f / HW) - m * m;
        g_mean[bc] = m;
        g_rsig[bc] = rsqrtf(var + EPS);
    }
}

// ---------------------------------------------------------------------------
// Weight prepack: conv_w [OUT][C][3][3] fp32 -> [tap][oc][ci] fp16
// ---------------------------------------------------------------------------
__global__ void prepack_kernel(const float* __restrict__ cw) {
    int idx = blockIdx.x * 256 + threadIdx.x;
    int tap = idx >> 16;
    int r   = idx & 0xFFFF;
    int oc  = r >> 8, ci = r & 255;
    g_wh[idx] = __float2half_rn(cw[(oc * C + ci) * 9 + tap]);
}

// ---------------------------------------------------------------------------
// K2 (R9): normalize + adaptive grouped 3x3 + 1x1 + bias -> fp16 NHWC padded.
// 32x32 tile, 128 threads, 8 px/thread, packed f32x2 fma.
// ---------------------------------------------------------------------------
constexpr int T2W = 32, T2H = 32;

__global__ __launch_bounds__(128, 4)
void ada_kernel(const float* __restrict__ x,
                const float* __restrict__ ws,
                const float* __restrict__ wp,
                const float* __restrict__ bias) {
    __shared__ float s_in[CPG][T2H + 2][35];   // stride 35: conflict-free
    __shared__ ull   s_w2[CPG][CPG][9];        // [o][j][k], weight duplicated
    __shared__ float s_wp[CPG][CPG];

    int bg = blockIdx.z;
    int b = bg >> 5, g = bg & 31;
    int x0 = blockIdx.x * T2W, y0 = blockIdx.y * T2H;
    int tid = threadIdx.x;

    if (tid < CPG * CPG) {
        int o = tid >> 3, i = tid & 7;
        s_wp[o][i] = wp[(b * C + g * CPG + o) * CPG + i];
    }
    __syncthreads();

    // fold 1x1 into spatial weights, store duplicated (w,w) pairs
    for (int t = tid; t < CPG * CPG * 9; t += 128) {
        int o = t / 72, r = t % 72, j = r / 9, k = r % 9;
        float acc = 0.f;
        #pragma unroll
        for (int i = 0; i < CPG; i++)
            acc += s_wp[o][i] * ws[((b * C + g * CPG + i) * CPG + j) * 9 + k];
        s_w2[o][j][k] = pack2(acc, acc);
    }

    // normalized input tile with reflect halo: 8 ch x 34 x 34
    for (int e = tid; e < CPG * (T2H + 2) * 34; e += 128) {
        int j   = e / ((T2H + 2) * 34);
        int r   = (e / 34) % (T2H + 2);
        int col = e % 34;
        int gy = reflect_idx(y0 + r - 1, H);
        int gx = reflect_idx(x0 + col - 1, W);
        int cg = b * C + g * CPG + j;
        s_in[j][r][col] = (x[(size_t)cg * HW + gy * W + gx] - g_mean[cg]) * g_rsig[cg];
    }
    __syncthreads();

    int px = (tid & 3) * 8;     // 0,8,16,24
    int py = tid >> 2;          // 0..31

    ull acc[CPG][4];
    #pragma unroll
    for (int o = 0; o < CPG; o++)
        #pragma unroll
        for (int q = 0; q < 4; q++)
            acc[o][q] = 0ull;

    #pragma unroll
    for (int j = 0; j < CPG; j++) {
        #pragma unroll
        for (int ky = 0; ky < 3; ky++) {
            const float* row = &s_in[j][py + ky][px];
            float in[10];
            #pragma unroll
            for (int k = 0; k < 10; k++) in[k] = row[k];
            ull P0[4], P1[4], P2[4];
            #pragma unroll
            for (int q = 0; q < 4; q++) {
                P0[q] = pack2(in[2 * q],     in[2 * q + 1]);
                P1[q] = pack2(in[2 * q + 1], in[2 * q + 2]);
            }
            P2[0] = P0[1]; P2[1] = P0[2]; P2[2] = P0[3];
            P2[3] = pack2(in[8], in[9]);
            #pragma unroll
            for (int o = 0; o < CPG; o++) {
                ull w0 = s_w2[o][j][ky * 3 + 0];
                ull w1 = s_w2[o][j][ky * 3 + 1];
                ull w2 = s_w2[o][j][ky * 3 + 2];
                #pragma unroll
                for (int q = 0; q < 4; q++) {
                    acc[o][q] = fma2(w0, P0[q], acc[o][q]);
                    acc[o][q] = fma2(w1, P1[q], acc[o][q]);
                    acc[o][q] = fma2(w2, P2[q], acc[o][q]);
                }
            }
        }
    }

    float bz[CPG];
    #pragma unroll
    for (int o = 0; o < CPG; o++) bz[o] = bias[b * C + g * CPG + o];

    union U16 { __half h[8]; uint4 u; };
    size_t pbase = ((size_t)(b * HP + (y0 + py + 1)) * WP + (x0 + px + 1)) * C
                   + g * CPG;
    #pragma unroll
    for (int q = 0; q < 4; q++) {
        U16 ua, ub;
        #pragma unroll
        for (int o = 0; o < CPG; o++) {
            float2 v = unpack2(acc[o][q]);
            ua.h[o] = __float2half_rn(v.x + bz[o]);
            ub.h[o] = __float2half_rn(v.y + bz[o]);
        }
        *reinterpret_cast<uint4*>(g_yh + pbase + (2 * q)     * C) = ua.u;
        *reinterpret_cast<uint4*>(g_yh + pbase + (2 * q + 1) * C) = ub.u;
    }
}

// ---------------------------------------------------------------------------
// Halo fill (reflect) for the padded NHWC plane
// ---------------------------------------------------------------------------
__global__ void halo_kernel() {
    int e = blockIdx.x;      // 0..515
    int b = blockIdx.y;
    int py, px;
    if (e < 130)       { py = 0;            px = e; }
    else if (e < 260)  { py = 129;          px = e - 130; }
    else if (e < 388)  { py = e - 260 + 1;  px = 0; }
    else               { py = e - 388 + 1;  px = 129; }
    int sy = reflect_idx(py - 1, H) + 1;
    int sx = reflect_idx(px - 1, W) + 1;
    size_t dst = ((size_t)(b * HP + py) * WP + px) * C + threadIdx.x;
    size_t src = ((size_t)(b * HP + sy) * WP + sx) * C + threadIdx.x;
    g_yh[dst] = g_yh[src];
}

// ---------------------------------------------------------------------------
// K3: fp16 implicit-GEMM final conv (R7/R9 config + k-step frag pipeline).
// CTA: 128 oc x 128 px, 8 warps (2M x 4N), warp tile 64x32, CCH=64,
// A double buffer 2x16KB + B double buffer 2x16.6KB.
// Fragments double-buffered: LDSMs for ks+1 issued before MMAs of ks.
// ---------------------------------------------------------------------------
constexpr int A_BUF  = 16384;
constexpr int OFF_A  = 0;
constexpr int B_BUF  = 130 * 128;
constexpr int OFF_B  = 32768;
constexpr int SMEM_K3 = OFF_B + 2 * B_BUF;       // 66048

__global__ __launch_bounds__(256, 2)
void final_mma_kernel(const float* __restrict__ cb, float* __restrict__ out) {
    extern __shared__ char sb[];
    uint32_t su = smem_u32(sb);
    int tid  = threadIdx.x;
    int warp = tid >> 5, lane = tid & 31;
    int wm = warp >> 2;
    int wn = warp & 3;

    int y0  = blockIdx.x;
    int b   = blockIdx.y;
    int ocb = blockIdx.z;

    int a_r[4], a_j[4];
    uint32_t a_soff[4];
    #pragma unroll
    for (int q = 0; q < 4; q++) {
        int e = tid + q * 256;
        a_r[q] = e >> 3; a_j[q] = e & 7;
        a_soff[q] = SWZ128((uint32_t)(a_r[q] * 128 + a_j[q] * 16));
    }

    auto issue_A = [&](int tap, int c0, uint32_t abase) {
        #pragma unroll
        for (int q = 0; q < 4; q++) {
            size_t gi = ((size_t)(tap * OUT + ocb * MTILE + a_r[q])) * C
                        + c0 + a_j[q] * 8;
            cpa16(abase + a_soff[q], g_wh + gi);
        }
    };
    auto issue_B = [&](int c0, int dyi, uint32_t bbase) {
        for (int e = tid; e < 130 * 8; e += 256) {
            int r = e >> 3, j = e & 7;
            size_t gi = ((size_t)(b * HP + y0 + dyi) * WP + r) * C + c0 + j * 8;
            uint32_t off = SWZ128((uint32_t)(r * 128 + j * 16));
            cpa16(bbase + off, g_yh + gi);
        }
    };

    float acc[4][4][4];
    #pragma unroll
    for (int mi = 0; mi < 4; mi++)
        #pragma unroll
        for (int ni = 0; ni < 4; ni++)
            #pragma unroll
            for (int q = 0; q < 4; q++)
                acc[mi][ni][q] = 0.f;

    uint32_t a_row = (uint32_t)(wm * 64 + (lane & 15));
    uint32_t a_kh  = (uint32_t)(lane >> 4) * 16;
    uint32_t b_row = (uint32_t)(wn * 32 + (lane & 7) + ((lane >> 4) << 3));
    uint32_t b_kh  = (uint32_t)((lane >> 3) & 1) * 16;

    issue_A(0, 0, su + OFF_A);
    issue_B(0, 0, su + OFF_B);
    CP_COMMIT();

    uint32_t aF[2][4][4], bF[2][2][4];

    for (int it = 0; it < 36; it++) {
        int gi  = it / 3;
        int dxi = it % 3;
        uint32_t abase = su + OFF_A + (it & 1) * A_BUF;
        uint32_t bbase = su + OFF_B + (gi & 1) * B_BUF;

        CP_WAIT0();
        __syncthreads();

        if (it + 1 < 36) {
            int nit = it + 1;
            issue_A(nit % 9, (nit / 9) * CCH, su + OFF_A + (nit & 1) * A_BUF);
        }
        if (dxi == 0 && gi + 1 < 12) {
            int ng = gi + 1;
            issue_B((ng / 3) * CCH, ng % 3, su + OFF_B + (ng & 1) * B_BUF);
        }
        CP_COMMIT();

        // preload k-step 0 fragments
        #pragma unroll
        for (int mi = 0; mi < 4; mi++) {
            uint32_t off = SWZ128((a_row + mi * 16) * 128 + a_kh);
            ldmx4(aF[0][mi], abase + off);
        }
        #pragma unroll
        for (int nh = 0; nh < 2; nh++) {
            uint32_t off = SWZ128((b_row + nh * 16 + dxi) * 128 + b_kh);
            ldmx4(bF[0][nh], bbase + off);
        }

        #pragma unroll
        for (int ks = 0; ks < 4; ks++) {
            int cur = ks & 1, nxt = cur ^ 1;
            if (ks < 3) {
                uint32_t kb = (uint32_t)(ks + 1) * 32;
                #pragma unroll
                for (int mi = 0; mi < 4; mi++) {
                    uint32_t off = SWZ128((a_row + mi * 16) * 128 + kb + a_kh);
                    ldmx4(aF[nxt][mi], abase + off);
                }
                #pragma unroll
                for (int nh = 0; nh < 2; nh++) {
                    uint32_t off = SWZ128((b_row + nh * 16 + dxi) * 128 + kb + b_kh);
                    ldmx4(bF[nxt][nh], bbase + off);
                }
            }
            #pragma unroll
            for (int mi = 0; mi < 4; mi++)
                #pragma unroll
                for (int ni = 0; ni < 4; ni++)
                    mma16816(acc[mi][ni], aF[cur][mi],
                             &bF[cur][ni >> 1][(ni & 1) * 2]);
        }
    }

    int row0 = lane >> 2;
    int col2 = (lane & 3) * 2;
    #pragma unroll
    for (int mi = 0; mi < 4; mi++) {
        int oc = ocb * MTILE + wm * 64 + mi * 16 + row0;
        float bz0 = cb[oc];
        float bz1 = cb[oc + 8];
        size_t base0 = (((size_t)(b * OUT + oc))     * H + y0) * W;
        size_t base1 = (((size_t)(b * OUT + oc + 8)) * H + y0) * W;
        #pragma unroll
        for (int ni = 0; ni < 4; ni++) {
            int px = wn * 32 + ni * 8 + col2;
            float2 v0 = { acc[mi][ni][0] + bz0, acc[mi][ni][1] + bz0 };
            float2 v1 = { acc[mi][ni][2] + bz1, acc[mi][ni][3] + bz1 };
            *reinterpret_cast<float2*>(out + base0 + px) = v0;
            *reinterpret_cast<float2*>(out + base1 + px) = v1;
        }
    }
}

// ---------------------------------------------------------------------------
extern "C" void kernel_launch(void* const* d_in, const int* in_sizes, int n_in,
                              void* d_out, int out_size) {
    const float* x    = (const float*)d_in[0];
    const float* ws   = (const float*)d_in[1];
    const float* wp   = (const float*)d_in[2];
    const float* bias = (const float*)d_in[3];
    const float* cw   = (const float*)d_in[4];
    const float* cb   = (const float*)d_in[5];
    float* out = (float*)d_out;

    cudaFuncSetAttribute(final_mma_kernel,
                         cudaFuncAttributeMaxDynamicSharedMemorySize, SMEM_K3);

    stats_kernel<<<B * C, 256>>>(x);
    prepack_kernel<<<9 * OUT * C / 256, 256>>>(cw);
    ada_kernel<<<dim3(W / T2W, H / T2H, B * G), 128>>>(x, ws, wp, bias);
    halo_kernel<<<dim3(516, B), 256>>>();
    final_mma_kernel<<<dim3(H, B, OUT / MTILE), 256, SMEM_K3>>>(cb, out);
}

// round 14
// speedup vs baseline: 1.1457x; 1.0101x over previous
#include <cuda_runtime.h>
#include <cuda_fp16.h>
#include <cstdint>

// ---------------------------------------------------------------------------
// AdaConv2d (sm_103, legacy mma.sync path):
//   K1 stats -> prepack (fp16 weights in mma-fragment layout) -> K2
//   instancenorm + adaptive grouped conv (fp16 y, NHWC reflect-pre-padded)
//   -> halo -> K3 fp16 implicit-GEMM final 3x3 conv.
// R14: A operand streamed from L1/L2 via fragment-layout LDG.128 (register
//      double buffer, prefetch +1 k-step) — no A smem traffic at all.
//      B stays on the R9 cp.async smem path. Barriers only at dy-group edges.
// ---------------------------------------------------------------------------

constexpr int B   = 8;
constexpr int C   = 256;
constexpr int H   = 128;
constexpr int W   = 128;
constexpr int G   = 32;
constexpr int CPG = 8;
constexpr int OUT = 256;
constexpr int HW  = H * W;
constexpr float EPS = 1e-5f;

constexpr int HP = H + 2;
constexpr int WP = W + 2;

constexpr int MTILE = 128;   // oc per CTA (K3)
constexpr int CCH   = 64;    // ci per smem stage (K3)

typedef unsigned long long ull;

// Device scratch
static __device__ float g_mean[B * C];
static __device__ float g_rsig[B * C];
static __device__ __half g_yh[(size_t)B * HP * WP * C];   // NHWC padded, fp16
// A in fragment layout: [tap][kc(16)][mblock(16)][lane(32)][8 halves]
static __device__ __half g_wA[9 * 16 * 16 * 32 * 8];

__device__ __forceinline__ int reflect_idx(int v, int n) {
    v = v < 0 ? -v : v;
    v = v >= n ? 2 * n - 2 - v : v;
    return v;
}

#define SWZ128(off) ((off) ^ (((off) >> 3) & 0x70))

__device__ __forceinline__ uint32_t smem_u32(const void* p) {
    uint32_t a;
    asm("{ .reg .u64 t; cvta.to.shared.u64 t, %1; cvt.u32.u64 %0, t; }"
        : "=r"(a) : "l"(p));
    return a;
}
__device__ __forceinline__ void cpa16(uint32_t dst, const void* src) {
    asm volatile("cp.async.cg.shared.global [%0], [%1], 16;"
                 :: "r"(dst), "l"(src));
}
#define CP_COMMIT() asm volatile("cp.async.commit_group;" ::: "memory")
#define CP_WAIT0()  asm volatile("cp.async.wait_group 0;" ::: "memory")

__device__ __forceinline__ void ldmx4(uint32_t* r, uint32_t addr) {
    asm volatile("ldmatrix.sync.aligned.m8n8.x4.shared.b16 {%0,%1,%2,%3}, [%4];"
                 : "=r"(r[0]), "=r"(r[1]), "=r"(r[2]), "=r"(r[3]) : "r"(addr));
}
__device__ __forceinline__ void mma16816(float* d, const uint32_t* a,
                                         const uint32_t* b) {
    asm volatile(
        "mma.sync.aligned.m16n8k16.row.col.f32.f16.f16.f32 "
        "{%0,%1,%2,%3},{%4,%5,%6,%7},{%8,%9},{%0,%1,%2,%3};"
        : "+f"(d[0]), "+f"(d[1]), "+f"(d[2]), "+f"(d[3])
        : "r"(a[0]), "r"(a[1]), "r"(a[2]), "r"(a[3]), "r"(b[0]), "r"(b[1]));
}

// packed f32x2 helpers (Blackwell base ISA, sm_100+)
__device__ __forceinline__ ull pack2(float lo, float hi) {
    ull d;
    asm("mov.b64 %0, {%1, %2};" : "=l"(d) : "f"(lo), "f"(hi));
    return d;
}
__device__ __forceinline__ ull fma2(ull a, ull b, ull c) {
    ull d;
    asm("fma.rn.f32x2 %0, %1, %2, %3;" : "=l"(d) : "l"(a), "l"(b), "l"(c));
    return d;
}
__device__ __forceinline__ float2 unpack2(ull v) {
    float2 r;
    asm("mov.b64 {%0, %1}, %2;" : "=f"(r.x), "=f"(r.y) : "l"(v));
    return r;
}

// ---------------------------------------------------------------------------
// K1: per-(b,c) mean / rsqrt(var+eps)
// ---------------------------------------------------------------------------
__global__ void stats_kernel(const float* __restrict__ x) {
    int bc = blockIdx.x;
    const float4* xp = reinterpret_cast<const float4*>(x + (size_t)bc * HW);
    float s = 0.f, ss = 0.f;
    #pragma unroll 4
    for (int i = threadIdx.x; i < HW / 4; i += 256) {
        float4 v = xp[i];
        s  += (v.x + v.y) + (v.z + v.w);
        ss += v.x * v.x + v.y * v.y + v.z * v.z + v.w * v.w;
    }
    #pragma unroll
    for (int o = 16; o; o >>= 1) {
        s  += __shfl_down_sync(0xFFFFFFFFu, s, o);
        ss += __shfl_down_sync(0xFFFFFFFFu, ss, o);
    }
    __shared__ float sh_s[8], sh_ss[8];
    int wid = threadIdx.x >> 5, lid = threadIdx.x & 31;
    if (lid == 0) { sh_s[wid] = s; sh_ss[wid] = ss; }
    __syncthreads();
    if (threadIdx.x == 0) {
        float ts = 0.f, tss = 0.f;
        #pragma unroll
        for (int i = 0; i < 8; i++) { ts += sh_s[i]; tss += sh_ss[i]; }
        float m   = ts * (1.f / HW);
        float var = tss * (1.f / HW) - m * m;
        g_mean[bc] = m;
        g_rsig[bc] = rsqrtf(var + EPS);
    }
}

// ---------------------------------------------------------------------------
// Weight prepack: conv_w [OUT][C][3][3] fp32 -> mma A-fragment layout fp16.
// Element (tap, kc, mb, lane, h): reg r=h>>1;
//   oc = mb*16 + (lane>>2) + (r&1)*8
//   ci = kc*16 + (lane&3)*2 + (h&1) + (r>>1)*8
// ---------------------------------------------------------------------------
__global__ void prepack_kernel(const float* __restrict__ cw) {
    int idx = blockIdx.x * 256 + threadIdx.x;        // 589824 total
    int h    = idx & 7;
    int lane = (idx >> 3) & 31;
    int mb   = (idx >> 8) & 15;
    int kc   = (idx >> 12) & 15;
    int tap  = idx >> 16;
    int r    = h >> 1;
    int oc   = mb * 16 + (lane >> 2) + (r & 1) * 8;
    int ci   = kc * 16 + (lane & 3) * 2 + (h & 1) + ((r >> 1) & 1) * 8;
    g_wA[idx] = __float2half_rn(cw[(oc * C + ci) * 9 + tap]);
}

// ---------------------------------------------------------------------------
// K2 (R9): normalize + adaptive grouped 3x3 + 1x1 + bias -> fp16 NHWC padded.
// 32x32 tile, 128 threads, 8 px/thread, packed f32x2 fma.
// ---------------------------------------------------------------------------
constexpr int T2W = 32, T2H = 32;

__global__ __launch_bounds__(128, 4)
void ada_kernel(const float* __restrict__ x,
                const float* __restrict__ ws,
                const float* __restrict__ wp,
                const float* __restrict__ bias) {
    __shared__ float s_in[CPG][T2H + 2][35];   // stride 35: conflict-free
    __shared__ ull   s_w2[CPG][CPG][9];        // [o][j][k], weight duplicated
    __shared__ float s_wp[CPG][CPG];

    int bg = blockIdx.z;
    int b = bg >> 5, g = bg & 31;
    int x0 = blockIdx.x * T2W, y0 = blockIdx.y * T2H;
    int tid = threadIdx.x;

    if (tid < CPG * CPG) {
        int o = tid >> 3, i = tid & 7;
        s_wp[o][i] = wp[(b * C + g * CPG + o) * CPG + i];
    }
    __syncthreads();

    for (int t = tid; t < CPG * CPG * 9; t += 128) {
        int o = t / 72, r = t % 72, j = r / 9, k = r % 9;
        float acc = 0.f;
        #pragma unroll
        for (int i = 0; i < CPG; i++)
            acc += s_wp[o][i] * ws[((b * C + g * CPG + i) * CPG + j) * 9 + k];
        s_w2[o][j][k] = pack2(acc, acc);
    }

    for (int e = tid; e < CPG * (T2H + 2) * 34; e += 128) {
        int j   = e / ((T2H + 2) * 34);
        int r   = (e / 34) % (T2H + 2);
        int col = e % 34;
        int gy = reflect_idx(y0 + r - 1, H);
        int gx = reflect_idx(x0 + col - 1, W);
        int cg = b * C + g * CPG + j;
        s_in[j][r][col] = (x[(size_t)cg * HW + gy * W + gx] - g_mean[cg]) * g_rsig[cg];
    }
    __syncthreads();

    int px = (tid & 3) * 8;     // 0,8,16,24
    int py = tid >> 2;          // 0..31

    ull acc[CPG][4];
    #pragma unroll
    for (int o = 0; o < CPG; o++)
        #pragma unroll
        for (int q = 0; q < 4; q++)
            acc[o][q] = 0ull;

    #pragma unroll
    for (int j = 0; j < CPG; j++) {
        #pragma unroll
        for (int ky = 0; ky < 3; ky++) {
            const float* row = &s_in[j][py + ky][px];
            float in[10];
            #pragma unroll
            for (int k = 0; k < 10; k++) in[k] = row[k];
            ull P0[4], P1[4], P2[4];
            #pragma unroll
            for (int q = 0; q < 4; q++) {
                P0[q] = pack2(in[2 * q],     in[2 * q + 1]);
                P1[q] = pack2(in[2 * q + 1], in[2 * q + 2]);
            }
            P2[0] = P0[1]; P2[1] = P0[2]; P2[2] = P0[3];
            P2[3] = pack2(in[8], in[9]);
            #pragma unroll
            for (int o = 0; o < CPG; o++) {
                ull w0 = s_w2[o][j][ky * 3 + 0];
                ull w1 = s_w2[o][j][ky * 3 + 1];
                ull w2 = s_w2[o][j][ky * 3 + 2];
                #pragma unroll
                for (int q = 0; q < 4; q++) {
                    acc[o][q] = fma2(w0, P0[q], acc[o][q]);
                    acc[o][q] = fma2(w1, P1[q], acc[o][q]);
                    acc[o][q] = fma2(w2, P2[q], acc[o][q]);
                }
            }
        }
    }

    float bz[CPG];
    #pragma unroll
    for (int o = 0; o < CPG; o++) bz[o] = bias[b * C + g * CPG + o];

    union U16 { __half h[8]; uint4 u; };
    size_t pbase = ((size_t)(b * HP + (y0 + py + 1)) * WP + (x0 + px + 1)) * C
                   + g * CPG;
    #pragma unroll
    for (int q = 0; q < 4; q++) {
        U16 ua, ub;
        #pragma unroll
        for (int o = 0; o < CPG; o++) {
            float2 v = unpack2(acc[o][q]);
            ua.h[o] = __float2half_rn(v.x + bz[o]);
            ub.h[o] = __float2half_rn(v.y + bz[o]);
        }
        *reinterpret_cast<uint4*>(g_yh + pbase + (2 * q)     * C) = ua.u;
        *reinterpret_cast<uint4*>(g_yh + pbase + (2 * q + 1) * C) = ub.u;
    }
}

// ---------------------------------------------------------------------------
// Halo fill (reflect) for the padded NHWC plane
// ---------------------------------------------------------------------------
__global__ void halo_kernel() {
    int e = blockIdx.x;      // 0..515
    int b = blockIdx.y;
    int py, px;
    if (e < 130)       { py = 0;            px = e; }
    else if (e < 260)  { py = 129;          px = e - 130; }
    else if (e < 388)  { py = e - 260 + 1;  px = 0; }
    else               { py = e - 388 + 1;  px = 129; }
    int sy = reflect_idx(py - 1, H) + 1;
    int sx = reflect_idx(px - 1, W) + 1;
    size_t dst = ((size_t)(b * HP + py) * WP + px) * C + threadIdx.x;
    size_t src = ((size_t)(b * HP + sy) * WP + sx) * C + threadIdx.x;
    g_yh[dst] = g_yh[src];
}

// ---------------------------------------------------------------------------
// K3: fp16 implicit-GEMM final conv.
// CTA: 128 oc x 128 px, 8 warps (2M x 4N), warp tile 64x32, CCH=64.
// A: fragment-layout LDG.128 from L1/L2, register double buffer (+1 k-step).
// B: cp.async smem double buffer (reloaded per dy-group), inline LDSM.
// Barriers + commit/wait only at dy-group boundaries (12 of 36 iters).
// ---------------------------------------------------------------------------
constexpr int B_BUF  = 130 * 128;                // 16640
constexpr int OFF_B  = 0;
constexpr int SMEM_K3 = 2 * B_BUF;               // 33280

__global__ __launch_bounds__(256, 2)
void final_mma_kernel(const float* __restrict__ cb, float* __restrict__ out) {
    extern __shared__ char sb[];
    uint32_t su = smem_u32(sb);
    int tid  = threadIdx.x;
    int warp = tid >> 5, lane = tid & 31;
    int wm = warp >> 2;          // 0..1  -> oc base wm*64
    int wn = warp & 3;           // 0..3  -> px base wn*32

    int y0  = blockIdx.x;
    int b   = blockIdx.y;
    int ocb = blockIdx.z;

    const uint4* __restrict__ wA = reinterpret_cast<const uint4*>(g_wA);
    // per-thread constant fragment offset (uint4 units); mi adds 32
    int aconst = (ocb * 8 + wm * 4) * 32 + lane;

    auto issue_B = [&](int c0, int dyi, uint32_t bbase) {
        for (int e = tid; e < 130 * 8; e += 256) {
            int r = e >> 3, j = e & 7;
            size_t gi = ((size_t)(b * HP + y0 + dyi) * WP + r) * C + c0 + j * 8;
            uint32_t off = SWZ128((uint32_t)(r * 128 + j * 16));
            cpa16(bbase + off, g_yh + gi);
        }
    };

    float acc[4][4][4];
    #pragma unroll
    for (int mi = 0; mi < 4; mi++)
        #pragma unroll
        for (int ni = 0; ni < 4; ni++)
            #pragma unroll
            for (int q = 0; q < 4; q++)
                acc[mi][ni][q] = 0.f;

    uint32_t b_row = (uint32_t)(wn * 32 + (lane & 7) + ((lane >> 4) << 3));
    uint32_t b_kh  = (uint32_t)((lane >> 3) & 1) * 16;

    // prologue: B(group 0) + A fragments for (tap0, kc0)
    issue_B(0, 0, su + OFF_B);
    CP_COMMIT();

    uint4 aF[2][4];
    #pragma unroll
    for (int mi = 0; mi < 4; mi++)
        aF[0][mi] = wA[aconst + mi * 32];

    for (int it = 0; it < 36; it++) {
        int gi  = it / 3;              // dy-group (c0i*3 + dy)
        int dxi = it % 3;
        int tap = it % 9;
        int c0i = it / 9;

        if (dxi == 0) {
            CP_WAIT0();                // B(gi) landed
            __syncthreads();           // everyone done with buffer (gi+1)&1
            if (gi + 1 < 12) {
                int ng = gi + 1;
                issue_B((ng / 3) * CCH, ng % 3, su + OFF_B + (ng & 1) * B_BUF);
                CP_COMMIT();
            }
        }
        uint32_t bbase = su + OFF_B + (gi & 1) * B_BUF;

        int it_aoff = (tap * 16 + c0i * 4) * 512 + aconst;
        int nit = it + 1;
        int nx_aoff = ((nit % 9) * 16 + (nit / 9) * 4) * 512 + aconst;

        #pragma unroll
        for (int ks = 0; ks < 4; ks++) {
            int cur = ks & 1, nxt = cur ^ 1;
            // prefetch next k-step's A fragments (registers, via L1/L2)
            if (!(it == 35 && ks == 3)) {
                int poff = (ks < 3) ? (it_aoff + (ks + 1) * 512) : nx_aoff;
                #pragma unroll
                for (int mi = 0; mi < 4; mi++)
                    aF[nxt][mi] = wA[poff + mi * 32];
            }
            uint32_t kb = (uint32_t)ks * 32;
            uint32_t bF[2][4];
            #pragma unroll
            for (int nh = 0; nh < 2; nh++) {
                uint32_t off = SWZ128((b_row + nh * 16 + dxi) * 128 + kb + b_kh);
                ldmx4(bF[nh], bbase + off);
            }
            #pragma unroll
            for (int mi = 0; mi < 4; mi++)
                #pragma unroll
                for (int ni = 0; ni < 4; ni++)
                    mma16816(acc[mi][ni],
                             reinterpret_cast<const uint32_t*>(&aF[cur][mi]),
                             &bF[ni >> 1][(ni & 1) * 2]);
        }
    }

    // Epilogue: +bias, direct float2 stores
    int row0 = lane >> 2;
    int col2 = (lane & 3) * 2;
    #pragma unroll
    for (int mi = 0; mi < 4; mi++) {
        int oc = ocb * MTILE + wm * 64 + mi * 16 + row0;
        float bz0 = cb[oc];
        float bz1 = cb[oc + 8];
        size_t base0 = (((size_t)(b * OUT + oc))     * H + y0) * W;
        size_t base1 = (((size_t)(b * OUT + oc + 8)) * H + y0) * W;
        #pragma unroll
        for (int ni = 0; ni < 4; ni++) {
            int px = wn * 32 + ni * 8 + col2;
            float2 v0 = { acc[mi][ni][0] + bz0, acc[mi][ni][1] + bz0 };
            float2 v1 = { acc[mi][ni][2] + bz1, acc[mi][ni][3] + bz1 };
            *reinterpret_cast<float2*>(out + base0 + px) = v0;
            *reinterpret_cast<float2*>(out + base1 + px) = v1;
        }
    }
}

// ---------------------------------------------------------------------------
extern "C" void kernel_launch(void* const* d_in, const int* in_sizes, int n_in,
                              void* d_out, int out_size) {
    const float* x    = (const float*)d_in[0];
    const float* ws   = (const float*)d_in[1];
    const float* wp   = (const float*)d_in[2];
    const float* bias = (const float*)d_in[3];
    const float* cw   = (const float*)d_in[4];
    const float* cb   = (const float*)d_in[5];
    float* out = (float*)d_out;

    cudaFuncSetAttribute(final_mma_kernel,
                         cudaFuncAttributeMaxDynamicSharedMemorySize, SMEM_K3);

    stats_kernel<<<B * C, 256>>>(x);
    prepack_kernel<<<9 * 16 * 16 * 32 * 8 / 256, 256>>>(cw);
    ada_kernel<<<dim3(W / T2W, H / T2H, B * G), 128>>>(x, ws, wp, bias);
    halo_kernel<<<dim3(516, B), 256>>>();
    final_mma_kernel<<<dim3(H, B, OUT / MTILE), 256, SMEM_K3>>>(cb, out);
}

// round 15
// speedup vs baseline: 1.1711x; 1.0221x over previous
#include <cuda_runtime.h>
#include <cuda_fp16.h>
#include <cstdint>

// ---------------------------------------------------------------------------
// AdaConv2d (sm_103, legacy mma.sync path):
//   K1 stats+prepack (fused) -> K2 instancenorm + adaptive grouped conv
//   (fp16 y, NHWC reflect-pre-padded) -> halo -> K3 fp16 implicit-GEMM.
// R15: exact R9 configuration (best known: 645.6us) + prepack fused into the
//      stats launch. K3 structural experiments (R10/R12/R14) were all neutral
//      or regressions -> K3 is at the legacy-HMMA issue floor; keep R9's K3.
// ---------------------------------------------------------------------------

constexpr int B   = 8;
constexpr int C   = 256;
constexpr int H   = 128;
constexpr int W   = 128;
constexpr int G   = 32;
constexpr int CPG = 8;
constexpr int OUT = 256;
constexpr int HW  = H * W;
constexpr float EPS = 1e-5f;

constexpr int HP = H + 2;
constexpr int WP = W + 2;

constexpr int MTILE = 128;   // oc per CTA (K3)
constexpr int CCH   = 64;    // ci per smem stage (K3)

typedef unsigned long long ull;

// Device scratch
static __device__ float g_mean[B * C];
static __device__ float g_rsig[B * C];
static __device__ __half g_yh[(size_t)B * HP * WP * C];   // NHWC padded, fp16
static __device__ __half g_wh[9 * OUT * C];               // [tap][oc][ci] fp16

__device__ __forceinline__ int reflect_idx(int v, int n) {
    v = v < 0 ? -v : v;
    v = v >= n ? 2 * n - 2 - v : v;
    return v;
}

#define SWZ128(off) ((off) ^ (((off) >> 3) & 0x70))

__device__ __forceinline__ uint32_t smem_u32(const void* p) {
    uint32_t a;
    asm("{ .reg .u64 t; cvta.to.shared.u64 t, %1; cvt.u32.u64 %0, t; }"
        : "=r"(a) : "l"(p));
    return a;
}
__device__ __forceinline__ void cpa16(uint32_t dst, const void* src) {
    asm volatile("cp.async.cg.shared.global [%0], [%1], 16;"
                 :: "r"(dst), "l"(src));
}
#define CP_COMMIT() asm volatile("cp.async.commit_group;" ::: "memory")
#define CP_WAIT0()  asm volatile("cp.async.wait_group 0;" ::: "memory")

__device__ __forceinline__ void ldmx4(uint32_t* r, uint32_t addr) {
    asm volatile("ldmatrix.sync.aligned.m8n8.x4.shared.b16 {%0,%1,%2,%3}, [%4];"
                 : "=r"(r[0]), "=r"(r[1]), "=r"(r[2]), "=r"(r[3]) : "r"(addr));
}
__device__ __forceinline__ void mma16816(float* d, const uint32_t* a,
                                         const uint32_t* b) {
    asm volatile(
        "mma.sync.aligned.m16n8k16.row.col.f32.f16.f16.f32 "
        "{%0,%1,%2,%3},{%4,%5,%6,%7},{%8,%9},{%0,%1,%2,%3};"
        : "+f"(d[0]), "+f"(d[1]), "+f"(d[2]), "+f"(d[3])
        : "r"(a[0]), "r"(a[1]), "r"(a[2]), "r"(a[3]), "r"(b[0]), "r"(b[1]));
}

// packed f32x2 helpers (Blackwell base ISA, sm_100+)
__device__ __forceinline__ ull pack2(float lo, float hi) {
    ull d;
    asm("mov.b64 %0, {%1, %2};" : "=l"(d) : "f"(lo), "f"(hi));
    return d;
}
__device__ __forceinline__ ull fma2(ull a, ull b, ull c) {
    ull d;
    asm("fma.rn.f32x2 %0, %1, %2, %3;" : "=l"(d) : "l"(a), "l"(b), "l"(c));
    return d;
}
__device__ __forceinline__ float2 unpack2(ull v) {
    float2 r;
    asm("mov.b64 {%0, %1}, %2;" : "=f"(r.x), "=f"(r.y) : "l"(v));
    return r;
}

// ---------------------------------------------------------------------------
// K1: per-(b,c) mean / rsqrt(var+eps), with weight prepack fused in as
// extra blocks (blockIdx.x >= B*C): conv_w fp32 -> [tap][oc][ci] fp16.
// ---------------------------------------------------------------------------
constexpr int PREP_BLOCKS = 9 * OUT * C / 256;   // 2304

__global__ void stats_prepack_kernel(const float* __restrict__ x,
                                     const float* __restrict__ cw) {
    if (blockIdx.x >= (unsigned)(B * C)) {
        int idx = (blockIdx.x - B * C) * 256 + threadIdx.x;
        int tap = idx >> 16;
        int r   = idx & 0xFFFF;
        int oc  = r >> 8, ci = r & 255;
        g_wh[idx] = __float2half_rn(cw[(oc * C + ci) * 9 + tap]);
        return;
    }
    int bc = blockIdx.x;
    const float4* xp = reinterpret_cast<const float4*>(x + (size_t)bc * HW);
    float s = 0.f, ss = 0.f;
    #pragma unroll 4
    for (int i = threadIdx.x; i < HW / 4; i += 256) {
        float4 v = xp[i];
        s  += (v.x + v.y) + (v.z + v.w);
        ss += v.x * v.x + v.y * v.y + v.z * v.z + v.w * v.w;
    }
    #pragma unroll
    for (int o = 16; o; o >>= 1) {
        s  += __shfl_down_sync(0xFFFFFFFFu, s, o);
        ss += __shfl_down_sync(0xFFFFFFFFu, ss, o);
    }
    __shared__ float sh_s[8], sh_ss[8];
    int wid = threadIdx.x >> 5, lid = threadIdx.x & 31;
    if (lid == 0) { sh_s[wid] = s; sh_ss[wid] = ss; }
    __syncthreads();
    if (threadIdx.x == 0) {
        float ts = 0.f, tss = 0.f;
        #pragma unroll
        for (int i = 0; i < 8; i++) { ts += sh_s[i]; tss += sh_ss[i]; }
        float m   = ts * (1.f / HW);
        float var = tss * (1.f / HW) - m * m;
        g_mean[bc] = m;
        g_rsig[bc] = rsqrtf(var + EPS);
    }
}

// ---------------------------------------------------------------------------
// K2 (R9): normalize + adaptive grouped 3x3 + 1x1 + bias -> fp16 NHWC padded.
// 32x32 tile, 128 threads, 8 px/thread, packed f32x2 fma.
// ---------------------------------------------------------------------------
constexpr int T2W = 32, T2H = 32;

__global__ __launch_bounds__(128, 4)
void ada_kernel(const float* __restrict__ x,
                const float* __restrict__ ws,
                const float* __restrict__ wp,
                const float* __restrict__ bias) {
    __shared__ float s_in[CPG][T2H + 2][35];   // stride 35: conflict-free
    __shared__ ull   s_w2[CPG][CPG][9];        // [o][j][k], weight duplicated
    __shared__ float s_wp[CPG][CPG];

    int bg = blockIdx.z;
    int b = bg >> 5, g = bg & 31;
    int x0 = blockIdx.x * T2W, y0 = blockIdx.y * T2H;
    int tid = threadIdx.x;

    if (tid < CPG * CPG) {
        int o = tid >> 3, i = tid & 7;
        s_wp[o][i] = wp[(b * C + g * CPG + o) * CPG + i];
    }
    __syncthreads();

    // fold 1x1 into spatial weights, store duplicated (w,w) pairs
    for (int t = tid; t < CPG * CPG * 9; t += 128) {
        int o = t / 72, r = t % 72, j = r / 9, k = r % 9;
        float acc = 0.f;
        #pragma unroll
        for (int i = 0; i < CPG; i++)
            acc += s_wp[o][i] * ws[((b * C + g * CPG + i) * CPG + j) * 9 + k];
        s_w2[o][j][k] = pack2(acc, acc);
    }

    // normalized input tile with reflect halo: 8 ch x 34 x 34
    for (int e = tid; e < CPG * (T2H + 2) * 34; e += 128) {
        int j   = e / ((T2H + 2) * 34);
        int r   = (e / 34) % (T2H + 2);
        int col = e % 34;
        int gy = reflect_idx(y0 + r - 1, H);
        int gx = reflect_idx(x0 + col - 1, W);
        int cg = b * C + g * CPG + j;
        s_in[j][r][col] = (x[(size_t)cg * HW + gy * W + gx] - g_mean[cg]) * g_rsig[cg];
    }
    __syncthreads();

    int px = (tid & 3) * 8;     // 0,8,16,24
    int py = tid >> 2;          // 0..31

    ull acc[CPG][4];
    #pragma unroll
    for (int o = 0; o < CPG; o++)
        #pragma unroll
        for (int q = 0; q < 4; q++)
            acc[o][q] = 0ull;

    #pragma unroll
    for (int j = 0; j < CPG; j++) {
        #pragma unroll
        for (int ky = 0; ky < 3; ky++) {
            const float* row = &s_in[j][py + ky][px];
            float in[10];
            #pragma unroll
            for (int k = 0; k < 10; k++) in[k] = row[k];
            ull P0[4], P1[4], P2[4];
            #pragma unroll
            for (int q = 0; q < 4; q++) {
                P0[q] = pack2(in[2 * q],     in[2 * q + 1]);
                P1[q] = pack2(in[2 * q + 1], in[2 * q + 2]);
            }
            P2[0] = P0[1]; P2[1] = P0[2]; P2[2] = P0[3];
            P2[3] = pack2(in[8], in[9]);
            #pragma unroll
            for (int o = 0; o < CPG; o++) {
                ull w0 = s_w2[o][j][ky * 3 + 0];
                ull w1 = s_w2[o][j][ky * 3 + 1];
                ull w2 = s_w2[o][j][ky * 3 + 2];
                #pragma unroll
                for (int q = 0; q < 4; q++) {
                    acc[o][q] = fma2(w0, P0[q], acc[o][q]);
                    acc[o][q] = fma2(w1, P1[q], acc[o][q]);
                    acc[o][q] = fma2(w2, P2[q], acc[o][q]);
                }
            }
        }
    }

    float bz[CPG];
    #pragma unroll
    for (int o = 0; o < CPG; o++) bz[o] = bias[b * C + g * CPG + o];

    union U16 { __half h[8]; uint4 u; };
    size_t pbase = ((size_t)(b * HP + (y0 + py + 1)) * WP + (x0 + px + 1)) * C
                   + g * CPG;
    #pragma unroll
    for (int q = 0; q < 4; q++) {
        U16 ua, ub;
        #pragma unroll
        for (int o = 0; o < CPG; o++) {
            float2 v = unpack2(acc[o][q]);
            ua.h[o] = __float2half_rn(v.x + bz[o]);
            ub.h[o] = __float2half_rn(v.y + bz[o]);
        }
        *reinterpret_cast<uint4*>(g_yh + pbase + (2 * q)     * C) = ua.u;
        *reinterpret_cast<uint4*>(g_yh + pbase + (2 * q + 1) * C) = ub.u;
    }
}

// ---------------------------------------------------------------------------
// Halo fill (reflect) for the padded NHWC plane
// ---------------------------------------------------------------------------
__global__ void halo_kernel() {
    int e = blockIdx.x;      // 0..515
    int b = blockIdx.y;
    int py, px;
    if (e < 130)       { py = 0;            px = e; }
    else if (e < 260)  { py = 129;          px = e - 130; }
    else if (e < 388)  { py = e - 260 + 1;  px = 0; }
    else               { py = e - 388 + 1;  px = 129; }
    int sy = reflect_idx(py - 1, H) + 1;
    int sx = reflect_idx(px - 1, W) + 1;
    size_t dst = ((size_t)(b * HP + py) * WP + px) * C + threadIdx.x;
    size_t src = ((size_t)(b * HP + sy) * WP + sx) * C + threadIdx.x;
    g_yh[dst] = g_yh[src];
}

// ---------------------------------------------------------------------------
// K3 (R9, best known): fp16 implicit-GEMM final conv, cp.async pipelined.
// CTA: 128 oc x 128 px, 8 warps (2M x 4N), warp tile 64x32, CCH=64,
// A double buffer 2x16KB + B double buffer 2x16.6KB.
// ---------------------------------------------------------------------------
constexpr int A_BUF  = 16384;
constexpr int OFF_A  = 0;
constexpr int B_BUF  = 130 * 128;
constexpr int OFF_B  = 32768;
constexpr int SMEM_K3 = OFF_B + 2 * B_BUF;       // 66048

__global__ __launch_bounds__(256, 2)
void final_mma_kernel(const float* __restrict__ cb, float* __restrict__ out) {
    extern __shared__ char sb[];
    uint32_t su = smem_u32(sb);
    int tid  = threadIdx.x;
    int warp = tid >> 5, lane = tid & 31;
    int wm = warp >> 2;
    int wn = warp & 3;

    int y0  = blockIdx.x;
    int b   = blockIdx.y;
    int ocb = blockIdx.z;

    int a_r[4], a_j[4];
    uint32_t a_soff[4];
    #pragma unroll
    for (int q = 0; q < 4; q++) {
        int e = tid + q * 256;
        a_r[q] = e >> 3; a_j[q] = e & 7;
        a_soff[q] = SWZ128((uint32_t)(a_r[q] * 128 + a_j[q] * 16));
    }

    auto issue_A = [&](int tap, int c0, uint32_t abase) {
        #pragma unroll
        for (int q = 0; q < 4; q++) {
            size_t gi = ((size_t)(tap * OUT + ocb * MTILE + a_r[q])) * C
                        + c0 + a_j[q] * 8;
            cpa16(abase + a_soff[q], g_wh + gi);
        }
    };
    auto issue_B = [&](int c0, int dyi, uint32_t bbase) {
        for (int e = tid; e < 130 * 8; e += 256) {
            int r = e >> 3, j = e & 7;
            size_t gi = ((size_t)(b * HP + y0 + dyi) * WP + r) * C + c0 + j * 8;
            uint32_t off = SWZ128((uint32_t)(r * 128 + j * 16));
            cpa16(bbase + off, g_yh + gi);
        }
    };

    float acc[4][4][4];
    #pragma unroll
    for (int mi = 0; mi < 4; mi++)
        #pragma unroll
        for (int ni = 0; ni < 4; ni++)
            #pragma unroll
            for (int q = 0; q < 4; q++)
                acc[mi][ni][q] = 0.f;

    uint32_t a_row = (uint32_t)(wm * 64 + (lane & 15));
    uint32_t a_kh  = (uint32_t)(lane >> 4) * 16;
    uint32_t b_row = (uint32_t)(wn * 32 + (lane & 7) + ((lane >> 4) << 3));
    uint32_t b_kh  = (uint32_t)((lane >> 3) & 1) * 16;

    issue_A(0, 0, su + OFF_A);
    issue_B(0, 0, su + OFF_B);
    CP_COMMIT();

    for (int it = 0; it < 36; it++) {
        int gi  = it / 3;
        int dxi = it % 3;
        uint32_t abase = su + OFF_A + (it & 1) * A_BUF;
        uint32_t bbase = su + OFF_B + (gi & 1) * B_BUF;

        CP_WAIT0();
        __syncthreads();

        if (it + 1 < 36) {
            int nit = it + 1;
            issue_A(nit % 9, (nit / 9) * CCH, su + OFF_A + (nit & 1) * A_BUF);
        }
        if (dxi == 0 && gi + 1 < 12) {
            int ng = gi + 1;
            issue_B((ng / 3) * CCH, ng % 3, su + OFF_B + (ng & 1) * B_BUF);
        }
        CP_COMMIT();

        #pragma unroll
        for (int ks = 0; ks < 4; ks++) {
            uint32_t kb = (uint32_t)ks * 32;
            uint32_t aF[4][4], bF[2][4];
            #pragma unroll
            for (int mi = 0; mi < 4; mi++) {
                uint32_t off = SWZ128((a_row + mi * 16) * 128 + kb + a_kh);
                ldmx4(aF[mi], abase + off);
            }
            #pragma unroll
            for (int nh = 0; nh < 2; nh++) {
                uint32_t off = SWZ128((b_row + nh * 16 + dxi) * 128 + kb + b_kh);
                ldmx4(bF[nh], bbase + off);
            }
            #pragma unroll
            for (int mi = 0; mi < 4; mi++)
                #pragma unroll
                for (int ni = 0; ni < 4; ni++)
                    mma16816(acc[mi][ni], aF[mi], &bF[ni >> 1][(ni & 1) * 2]);
        }
    }

    int row0 = lane >> 2;
    int col2 = (lane & 3) * 2;
    #pragma unroll
    for (int mi = 0; mi < 4; mi++) {
        int oc = ocb * MTILE + wm * 64 + mi * 16 + row0;
        float bz0 = cb[oc];
        float bz1 = cb[oc + 8];
        size_t base0 = (((size_t)(b * OUT + oc))     * H + y0) * W;
        size_t base1 = (((size_t)(b * OUT + oc + 8)) * H + y0) * W;
        #pragma unroll
        for (int ni = 0; ni < 4; ni++) {
            int px = wn * 32 + ni * 8 + col2;
            float2 v0 = { acc[mi][ni][0] + bz0, acc[mi][ni][1] + bz0 };
            float2 v1 = { acc[mi][ni][2] + bz1, acc[mi][ni][3] + bz1 };
            *reinterpret_cast<float2*>(out + base0 + px) = v0;
            *reinterpret_cast<float2*>(out + base1 + px) = v1;
        }
    }
}

// ---------------------------------------------------------------------------
extern "C" void kernel_launch(void* const* d_in, const int* in_sizes, int n_in,
                              void* d_out, int out_size) {
    const float* x    = (const float*)d_in[0];
    const float* ws   = (const float*)d_in[1];
    const float* wp   = (const float*)d_in[2];
    const float* bias = (const float*)d_in[3];
    const float* cw   = (const float*)d_in[4];
    const float* cb   = (const float*)d_in[5];
    float* out = (float*)d_out;

    cudaFuncSetAttribute(final_mma_kernel,
                         cudaFuncAttributeMaxDynamicSharedMemorySize, SMEM_K3);

    stats_prepack_kernel<<<B * C + PREP_BLOCKS, 256>>>(x, cw);
    ada_kernel<<<dim3(W / T2W, H / T2H, B * G), 128>>>(x, ws, wp, bias);
    halo_kernel<<<dim3(516, B), 256>>>();
    final_mma_kernel<<<dim3(H, B, OUT / MTILE), 256, SMEM_K3>>>(cb, out);
}

// round 16
// speedup vs baseline: 1.1747x; 1.0031x over previous
#include <cuda_runtime.h>
#include <cuda_fp16.h>
#include <cstdint>

// ---------------------------------------------------------------------------
// AdaConv2d (sm_103, legacy mma.sync path):
//   K1 stats+prepack (fused) -> K2 instancenorm + adaptive grouped conv
//   (fp16 y, NHWC reflect-pre-padded) -> halo -> K3 fp16 implicit-GEMM.
// R16: K3 re-tiled to 4 warps x (64 oc x 64 px) warp tiles, 128 thr/CTA,
//      2 CTAs/SM -> 256 regs/thread budget. Fragment traffic per MMA drops
//      192B -> 128B (8 LDSM per 32 MMAs), clearing the L1TEX co-binding
//      (was 62% busy vs tensor 71%).
// ---------------------------------------------------------------------------

constexpr int B   = 8;
constexpr int C   = 256;
constexpr int H   = 128;
constexpr int W   = 128;
constexpr int G   = 32;
constexpr int CPG = 8;
constexpr int OUT = 256;
constexpr int HW  = H * W;
constexpr float EPS = 1e-5f;

constexpr int HP = H + 2;
constexpr int WP = W + 2;

constexpr int MTILE = 128;   // oc per CTA (K3)
constexpr int CCH   = 64;    // ci per smem stage (K3)

typedef unsigned long long ull;

// Device scratch
static __device__ float g_mean[B * C];
static __device__ float g_rsig[B * C];
static __device__ __half g_yh[(size_t)B * HP * WP * C];   // NHWC padded, fp16
static __device__ __half g_wh[9 * OUT * C];               // [tap][oc][ci] fp16

__device__ __forceinline__ int reflect_idx(int v, int n) {
    v = v < 0 ? -v : v;
    v = v >= n ? 2 * n - 2 - v : v;
    return v;
}

#define SWZ128(off) ((off) ^ (((off) >> 3) & 0x70))

__device__ __forceinline__ uint32_t smem_u32(const void* p) {
    uint32_t a;
    asm("{ .reg .u64 t; cvta.to.shared.u64 t, %1; cvt.u32.u64 %0, t; }"
        : "=r"(a) : "l"(p));
    return a;
}
__device__ __forceinline__ void cpa16(uint32_t dst, const void* src) {
    asm volatile("cp.async.cg.shared.global [%0], [%1], 16;"
                 :: "r"(dst), "l"(src));
}
#define CP_COMMIT() asm volatile("cp.async.commit_group;" ::: "memory")
#define CP_WAIT0()  asm volatile("cp.async.wait_group 0;" ::: "memory")

__device__ __forceinline__ void ldmx4(uint32_t* r, uint32_t addr) {
    asm volatile("ldmatrix.sync.aligned.m8n8.x4.shared.b16 {%0,%1,%2,%3}, [%4];"
                 : "=r"(r[0]), "=r"(r[1]), "=r"(r[2]), "=r"(r[3]) : "r"(addr));
}
__device__ __forceinline__ void mma16816(float* d, const uint32_t* a,
                                         const uint32_t* b) {
    asm volatile(
        "mma.sync.aligned.m16n8k16.row.col.f32.f16.f16.f32 "
        "{%0,%1,%2,%3},{%4,%5,%6,%7},{%8,%9},{%0,%1,%2,%3};"
        : "+f"(d[0]), "+f"(d[1]), "+f"(d[2]), "+f"(d[3])
        : "r"(a[0]), "r"(a[1]), "r"(a[2]), "r"(a[3]), "r"(b[0]), "r"(b[1]));
}

// packed f32x2 helpers (Blackwell base ISA, sm_100+)
__device__ __forceinline__ ull pack2(float lo, float hi) {
    ull d;
    asm("mov.b64 %0, {%1, %2};" : "=l"(d) : "f"(lo), "f"(hi));
    return d;
}
__device__ __forceinline__ ull fma2(ull a, ull b, ull c) {
    ull d;
    asm("fma.rn.f32x2 %0, %1, %2, %3;" : "=l"(d) : "l"(a), "l"(b), "l"(c));
    return d;
}
__device__ __forceinline__ float2 unpack2(ull v) {
    float2 r;
    asm("mov.b64 {%0, %1}, %2;" : "=f"(r.x), "=f"(r.y) : "l"(v));
    return r;
}

// ---------------------------------------------------------------------------
// K1: per-(b,c) mean / rsqrt(var+eps), with weight prepack fused in as
// extra blocks (blockIdx.x >= B*C): conv_w fp32 -> [tap][oc][ci] fp16.
// ---------------------------------------------------------------------------
constexpr int PREP_BLOCKS = 9 * OUT * C / 256;   // 2304

__global__ void stats_prepack_kernel(const float* __restrict__ x,
                                     const float* __restrict__ cw) {
    if (blockIdx.x >= (unsigned)(B * C)) {
        int idx = (blockIdx.x - B * C) * 256 + threadIdx.x;
        int tap = idx >> 16;
        int r   = idx & 0xFFFF;
        int oc  = r >> 8, ci = r & 255;
        g_wh[idx] = __float2half_rn(cw[(oc * C + ci) * 9 + tap]);
        return;
    }
    int bc = blockIdx.x;
    const float4* xp = reinterpret_cast<const float4*>(x + (size_t)bc * HW);
    float s = 0.f, ss = 0.f;
    #pragma unroll 4
    for (int i = threadIdx.x; i < HW / 4; i += 256) {
        float4 v = xp[i];
        s  += (v.x + v.y) + (v.z + v.w);
        ss += v.x * v.x + v.y * v.y + v.z * v.z + v.w * v.w;
    }
    #pragma unroll
    for (int o = 16; o; o >>= 1) {
        s  += __shfl_down_sync(0xFFFFFFFFu, s, o);
        ss += __shfl_down_sync(0xFFFFFFFFu, ss, o);
    }
    __shared__ float sh_s[8], sh_ss[8];
    int wid = threadIdx.x >> 5, lid = threadIdx.x & 31;
    if (lid == 0) { sh_s[wid] = s; sh_ss[wid] = ss; }
    __syncthreads();
    if (threadIdx.x == 0) {
        float ts = 0.f, tss = 0.f;
        #pragma unroll
        for (int i = 0; i < 8; i++) { ts += sh_s[i]; tss += sh_ss[i]; }
        float m   = ts * (1.f / HW);
        float var = tss * (1.f / HW) - m * m;
        g_mean[bc] = m;
        g_rsig[bc] = rsqrtf(var + EPS);
    }
}

// ---------------------------------------------------------------------------
// K2 (R9): normalize + adaptive grouped 3x3 + 1x1 + bias -> fp16 NHWC padded.
// 32x32 tile, 128 threads, 8 px/thread, packed f32x2 fma.
// ---------------------------------------------------------------------------
constexpr int T2W = 32, T2H = 32;

__global__ __launch_bounds__(128, 4)
void ada_kernel(const float* __restrict__ x,
                const float* __restrict__ ws,
                const float* __restrict__ wp,
                const float* __restrict__ bias) {
    __shared__ float s_in[CPG][T2H + 2][35];   // stride 35: conflict-free
    __shared__ ull   s_w2[CPG][CPG][9];        // [o][j][k], weight duplicated
    __shared__ float s_wp[CPG][CPG];

    int bg = blockIdx.z;
    int b = bg >> 5, g = bg & 31;
    int x0 = blockIdx.x * T2W, y0 = blockIdx.y * T2H;
    int tid = threadIdx.x;

    if (tid < CPG * CPG) {
        int o = tid >> 3, i = tid & 7;
        s_wp[o][i] = wp[(b * C + g * CPG + o) * CPG + i];
    }
    __syncthreads();

    for (int t = tid; t < CPG * CPG * 9; t += 128) {
        int o = t / 72, r = t % 72, j = r / 9, k = r % 9;
        float acc = 0.f;
        #pragma unroll
        for (int i = 0; i < CPG; i++)
            acc += s_wp[o][i] * ws[((b * C + g * CPG + i) * CPG + j) * 9 + k];
        s_w2[o][j][k] = pack2(acc, acc);
    }

    for (int e = tid; e < CPG * (T2H + 2) * 34; e += 128) {
        int j   = e / ((T2H + 2) * 34);
        int r   = (e / 34) % (T2H + 2);
        int col = e % 34;
        int gy = reflect_idx(y0 + r - 1, H);
        int gx = reflect_idx(x0 + col - 1, W);
        int cg = b * C + g * CPG + j;
        s_in[j][r][col] = (x[(size_t)cg * HW + gy * W + gx] - g_mean[cg]) * g_rsig[cg];
    }
    __syncthreads();

    int px = (tid & 3) * 8;     // 0,8,16,24
    int py = tid >> 2;          // 0..31

    ull acc[CPG][4];
    #pragma unroll
    for (int o = 0; o < CPG; o++)
        #pragma unroll
        for (int q = 0; q < 4; q++)
            acc[o][q] = 0ull;

    #pragma unroll
    for (int j = 0; j < CPG; j++) {
        #pragma unroll
        for (int ky = 0; ky < 3; ky++) {
            const float* row = &s_in[j][py + ky][px];
            float in[10];
            #pragma unroll
            for (int k = 0; k < 10; k++) in[k] = row[k];
            ull P0[4], P1[4], P2[4];
            #pragma unroll
            for (int q = 0; q < 4; q++) {
                P0[q] = pack2(in[2 * q],     in[2 * q + 1]);
                P1[q] = pack2(in[2 * q + 1], in[2 * q + 2]);
            }
            P2[0] = P0[1]; P2[1] = P0[2]; P2[2] = P0[3];
            P2[3] = pack2(in[8], in[9]);
            #pragma unroll
            for (int o = 0; o < CPG; o++) {
                ull w0 = s_w2[o][j][ky * 3 + 0];
                ull w1 = s_w2[o][j][ky * 3 + 1];
                ull w2 = s_w2[o][j][ky * 3 + 2];
                #pragma unroll
                for (int q = 0; q < 4; q++) {
                    acc[o][q] = fma2(w0, P0[q], acc[o][q]);
                    acc[o][q] = fma2(w1, P1[q], acc[o][q]);
                    acc[o][q] = fma2(w2, P2[q], acc[o][q]);
                }
            }
        }
    }

    float bz[CPG];
    #pragma unroll
    for (int o = 0; o < CPG; o++) bz[o] = bias[b * C + g * CPG + o];

    union U16 { __half h[8]; uint4 u; };
    size_t pbase = ((size_t)(b * HP + (y0 + py + 1)) * WP + (x0 + px + 1)) * C
                   + g * CPG;
    #pragma unroll
    for (int q = 0; q < 4; q++) {
        U16 ua, ub;
        #pragma unroll
        for (int o = 0; o < CPG; o++) {
            float2 v = unpack2(acc[o][q]);
            ua.h[o] = __float2half_rn(v.x + bz[o]);
            ub.h[o] = __float2half_rn(v.y + bz[o]);
        }
        *reinterpret_cast<uint4*>(g_yh + pbase + (2 * q)     * C) = ua.u;
        *reinterpret_cast<uint4*>(g_yh + pbase + (2 * q + 1) * C) = ub.u;
    }
}

// ---------------------------------------------------------------------------
// Halo fill (reflect) for the padded NHWC plane
// ---------------------------------------------------------------------------
__global__ void halo_kernel() {
    int e = blockIdx.x;      // 0..515
    int b = blockIdx.y;
    int py, px;
    if (e < 130)       { py = 0;            px = e; }
    else if (e < 260)  { py = 129;          px = e - 130; }
    else if (e < 388)  { py = e - 260 + 1;  px = 0; }
    else               { py = e - 388 + 1;  px = 129; }
    int sy = reflect_idx(py - 1, H) + 1;
    int sx = reflect_idx(px - 1, W) + 1;
    size_t dst = ((size_t)(b * HP + py) * WP + px) * C + threadIdx.x;
    size_t src = ((size_t)(b * HP + sy) * WP + sx) * C + threadIdx.x;
    g_yh[dst] = g_yh[src];
}

// ---------------------------------------------------------------------------
// K3 (R16): fp16 implicit-GEMM final conv, cp.async pipelined.
// CTA: 128 oc x 128 px, 4 warps (2M x 2N), warp tile 64x64, CCH=64.
// 8 LDSM per 32 MMAs -> 128 B/MMA fragment traffic (L1TEX relief).
// A double buffer 2x16KB + B double buffer 2x16.6KB. 2 CTAs/SM.
// ---------------------------------------------------------------------------
constexpr int A_BUF  = 16384;
constexpr int OFF_A  = 0;
constexpr int B_BUF  = 130 * 128;
constexpr int OFF_B  = 32768;
constexpr int SMEM_K3 = OFF_B + 2 * B_BUF;       // 66048

__global__ __launch_bounds__(128, 2)
void final_mma_kernel(const float* __restrict__ cb, float* __restrict__ out) {
    extern __shared__ char sb[];
    uint32_t su = smem_u32(sb);
    int tid  = threadIdx.x;
    int warp = tid >> 5, lane = tid & 31;
    int wm = warp >> 1;          // 0..1 -> oc base wm*64
    int wn = warp & 1;           // 0..1 -> px base wn*64

    int y0  = blockIdx.x;
    int b   = blockIdx.y;
    int ocb = blockIdx.z;

    // A staging: 1024 16B chunks, 8 per thread
    int a_r[8], a_j[8];
    uint32_t a_soff[8];
    #pragma unroll
    for (int q = 0; q < 8; q++) {
        int e = tid + q * 128;
        a_r[q] = e >> 3; a_j[q] = e & 7;
        a_soff[q] = SWZ128((uint32_t)(a_r[q] * 128 + a_j[q] * 16));
    }

    auto issue_A = [&](int tap, int c0, uint32_t abase) {
        #pragma unroll
        for (int q = 0; q < 8; q++) {
            size_t gi = ((size_t)(tap * OUT + ocb * MTILE + a_r[q])) * C
                        + c0 + a_j[q] * 8;
            cpa16(abase + a_soff[q], g_wh + gi);
        }
    };
    auto issue_B = [&](int c0, int dyi, uint32_t bbase) {
        for (int e = tid; e < 130 * 8; e += 128) {
            int r = e >> 3, j = e & 7;
            size_t gi = ((size_t)(b * HP + y0 + dyi) * WP + r) * C + c0 + j * 8;
            uint32_t off = SWZ128((uint32_t)(r * 128 + j * 16));
            cpa16(bbase + off, g_yh + gi);
        }
    };

    float acc[4][8][4];
    #pragma unroll
    for (int mi = 0; mi < 4; mi++)
        #pragma unroll
        for (int ni = 0; ni < 8; ni++)
            #pragma unroll
            for (int q = 0; q < 4; q++)
                acc[mi][ni][q] = 0.f;

    uint32_t a_row = (uint32_t)(wm * 64 + (lane & 15));
    uint32_t a_kh  = (uint32_t)(lane >> 4) * 16;
    uint32_t b_row = (uint32_t)(wn * 64 + (lane & 7) + ((lane >> 4) << 3));
    uint32_t b_kh  = (uint32_t)((lane >> 3) & 1) * 16;

    issue_A(0, 0, su + OFF_A);
    issue_B(0, 0, su + OFF_B);
    CP_COMMIT();

    for (int it = 0; it < 36; it++) {
        int gi  = it / 3;
        int dxi = it % 3;
        uint32_t abase = su + OFF_A + (it & 1) * A_BUF;
        uint32_t bbase = su + OFF_B + (gi & 1) * B_BUF;

        CP_WAIT0();
        __syncthreads();

        if (it + 1 < 36) {
            int nit = it + 1;
            issue_A(nit % 9, (nit / 9) * CCH, su + OFF_A + (nit & 1) * A_BUF);
        }
        if (dxi == 0 && gi + 1 < 12) {
            int ng = gi + 1;
            issue_B((ng / 3) * CCH, ng % 3, su + OFF_B + (ng & 1) * B_BUF);
        }
        CP_COMMIT();

        #pragma unroll
        for (int ks = 0; ks < 4; ks++) {
            uint32_t kb = (uint32_t)ks * 32;
            uint32_t aF[4][4], bF[4][4];
            #pragma unroll
            for (int mi = 0; mi < 4; mi++) {
                uint32_t off = SWZ128((a_row + mi * 16) * 128 + kb + a_kh);
                ldmx4(aF[mi], abase + off);
            }
            #pragma unroll
            for (int nh = 0; nh < 4; nh++) {
                uint32_t off = SWZ128((b_row + nh * 16 + dxi) * 128 + kb + b_kh);
                ldmx4(bF[nh], bbase + off);
            }
            #pragma unroll
            for (int mi = 0; mi < 4; mi++)
                #pragma unroll
                for (int ni = 0; ni < 8; ni++)
                    mma16816(acc[mi][ni], aF[mi], &bF[ni >> 1][(ni & 1) * 2]);
        }
    }

    // Epilogue: +bias, direct float2 stores
    int row0 = lane >> 2;
    int col2 = (lane & 3) * 2;
    #pragma unroll
    for (int mi = 0; mi < 4; mi++) {
        int oc = ocb * MTILE + wm * 64 + mi * 16 + row0;
        float bz0 = cb[oc];
        float bz1 = cb[oc + 8];
        size_t base0 = (((size_t)(b * OUT + oc))     * H + y0) * W;
        size_t base1 = (((size_t)(b * OUT + oc + 8)) * H + y0) * W;
        #pragma unroll
        for (int ni = 0; ni < 8; ni++) {
            int px = wn * 64 + ni * 8 + col2;
            float2 v0 = { acc[mi][ni][0] + bz0, acc[mi][ni][1] + bz0 };
            float2 v1 = { acc[mi][ni][2] + bz1, acc[mi][ni][3] + bz1 };
            *reinterpret_cast<float2*>(out + base0 + px) = v0;
            *reinterpret_cast<float2*>(out + base1 + px) = v1;
        }
    }
}

// ---------------------------------------------------------------------------
extern "C" void kernel_launch(void* const* d_in, const int* in_sizes, int n_in,
                              void* d_out, int out_size) {
    const float* x    = (const float*)d_in[0];
    const float* ws   = (const float*)d_in[1];
    const float* wp   = (const float*)d_in[2];
    const float* bias = (const float*)d_in[3];
    const float* cw   = (const float*)d_in[4];
    const float* cb   = (const float*)d_in[5];
    float* out = (float*)d_out;

    cudaFuncSetAttribute(final_mma_kernel,
                         cudaFuncAttributeMaxDynamicSharedMemorySize, SMEM_K3);

    stats_prepack_kernel<<<B * C + PREP_BLOCKS, 256>>>(x, cw);
    ada_kernel<<<dim3(W / T2W, H / T2H, B * G), 128>>>(x, ws, wp, bias);
    halo_kernel<<<dim3(516, B), 256>>>();
    final_mma_kernel<<<dim3(H, B, OUT / MTILE), 128, SMEM_K3>>>(cb, out);
}